// round 7
// baseline (speedup 1.0000x reference)
#include <cuda_runtime.h>
#include <cuda_bf16.h>
#include <cstdint>
#include <cstddef>
#include <math_constants.h>

// Problem constants
#define Bz 64
#define Sq 128
#define Hd 1024
#define Ad 512
#define Ed 512
#define Vv 32000

#define NSPLIT 8      // split-K for gates GEMMs
#define DPSPLIT 4     // split-K for dec_proj
#define NEB 4         // energy column-blocks (512/128) -> score partials

// Scratch layout (floats)
#define OFF_DPP      0u                        // DPSPLIT*64*512 = 131072
#define OFF_DP       131072u                   // 64*512         = 32768
#define OFF_SCOREP   163840u                   // NEB*128*64     = 32768
#define OFF_X0       196608u                   // 64*2560        = 163840
#define OFF_GATES    360448u                   // NSPLIT*64*4096 = 2097152
#define OFF_H0       2457600u                  // 64*1024        = 65536
#define OFF_FCIN     2523136u                  // 64*3072        = 196608
#define SCRATCH_TOTAL 2719744u

__device__ float g_scratch[SCRATCH_TOTAL];

#define BK 32
#define LDSW (BK + 4)   // padded smem row (floats)

// ---------------------------------------------------------------------------
// helpers
// ---------------------------------------------------------------------------
__device__ __forceinline__ uint32_t f2tf32(float x) {
    uint32_t r;
    asm("cvt.rna.tf32.f32 %0, %1;" : "=r"(r) : "f"(x));
    return r;
}

__device__ __forceinline__ float tanh_fast(float x) {
    float y;
    asm("tanh.approx.f32 %0, %1;" : "=f"(y) : "f"(x));
    return y;
}

__device__ __forceinline__ void mma_tf32(float c[4], const uint32_t a[4], const uint32_t b[2]) {
    asm volatile(
        "mma.sync.aligned.m16n8k8.row.col.f32.tf32.tf32.f32 "
        "{%0,%1,%2,%3}, {%4,%5,%6,%7}, {%8,%9}, {%0,%1,%2,%3};\n"
        : "+f"(c[0]), "+f"(c[1]), "+f"(c[2]), "+f"(c[3])
        : "r"(a[0]), "r"(a[1]), "r"(a[2]), "r"(a[3]), "r"(b[0]), "r"(b[1]));
}

__device__ __forceinline__ void cp16(float* dst_smem, const float* src_gmem) {
    uint32_t sm = (uint32_t)__cvta_generic_to_shared(dst_smem);
    asm volatile("cp.async.cg.shared.global [%0], [%1], 16;\n" :: "r"(sm), "l"(src_gmem));
}
__device__ __forceinline__ void cp_commit() {
    asm volatile("cp.async.commit_group;\n");
}
__device__ __forceinline__ void cp_wait1() {
    asm volatile("cp.async.wait_group 1;\n");
}

// ---------------------------------------------------------------------------
// Pipelined tf32 GEMM with optional split-K and optional fused score epilogue.
// C[M,N] = sum_seg A_seg(M,Kseg) * B_seg(N,Kseg)^T (+bias). Row-major, ld==K.
// If score_parts != nullptr (requires BM==64, m0 % 64 == 0): instead of
// storing C, computes p[b] = sum_col tanh(acc[b,col] + dp[b,col]) * vw[col]
// over this block's BN columns and writes score_parts[bx][s][b], s = m0/64.
// ---------------------------------------------------------------------------
template<int BM, int BN, int WN, int STAGES>
__global__ void __launch_bounds__(256, 1)
gemm_cp(const float* __restrict__ A,  const float* __restrict__ B,  int K1,
        const float* __restrict__ A2, const float* __restrict__ B2, int K2,
        const float* __restrict__ bias, float* __restrict__ C, int N,
        int tpz, int zstride,
        const float* __restrict__ dp, const float* __restrict__ vw,
        float* __restrict__ score_parts)
{
    constexpr int NWM = BM / 32;
    constexpr int NI  = WN / 8;
    constexpr int STAGE_F = (BM + BN) * LDSW;

    extern __shared__ float smem[];

    const int tid  = threadIdx.x;
    const int warp = tid >> 5;
    const int lane = tid & 31;
    const int wm = warp % NWM;
    const int wn = warp / NWM;
    const int g  = lane >> 2;
    const int tg = lane & 3;

    const int m0 = blockIdx.y * BM;
    const int n0 = blockIdx.x * BN;

    C += (size_t)blockIdx.z * zstride;

    float acc[2][NI][4];
#pragma unroll
    for (int mi = 0; mi < 2; mi++)
#pragma unroll
        for (int ni = 0; ni < NI; ni++)
#pragma unroll
            for (int r = 0; r < 4; r++) acc[mi][ni][r] = 0.0f;

    const int T1 = K1 / BK;
    const int T  = T1 + ((A2 != nullptr) ? (K2 / BK) : 0);
    const int tb = blockIdx.z * tpz;
    const int te = (tb + tpz < T) ? (tb + tpz) : T;

    auto load_stage = [&](int t) {
        const float* Ap; const float* Bp; int ld, off;
        if (t < T1) { Ap = A;  Bp = B;  ld = K1; off = t * BK; }
        else        { Ap = A2; Bp = B2; ld = K2; off = (t - T1) * BK; }
        float* as = smem + (t % STAGES) * STAGE_F;
        float* bs = as + BM * LDSW;
#pragma unroll
        for (int i = 0; i < BM / 32; i++) {
            int id = tid + i * 256;
            int r  = id >> 3;
            int c4 = (id & 7) * 4;
            cp16(as + r * LDSW + c4, Ap + (size_t)(m0 + r) * ld + off + c4);
        }
#pragma unroll
        for (int i = 0; i < BN / 32; i++) {
            int id = tid + i * 256;
            int r  = id >> 3;
            int c4 = (id & 7) * 4;
            cp16(bs + r * LDSW + c4, Bp + (size_t)(n0 + r) * ld + off + c4);
        }
        cp_commit();
    };

#pragma unroll
    for (int s = 0; s < STAGES - 1; s++) {
        if (tb + s < te) load_stage(tb + s); else cp_commit();
    }

    for (int t = tb; t < te; t++) {
        cp_wait1();
        __syncthreads();

        int nt = t + STAGES - 1;
        if (nt < te) load_stage(nt); else cp_commit();

        const float* as = smem + (t % STAGES) * STAGE_F;
        const float* bs = as + BM * LDSW;

#pragma unroll
        for (int ks = 0; ks < BK; ks += 8) {
            uint32_t af[2][4];
            uint32_t bf[NI][2];
#pragma unroll
            for (int mi = 0; mi < 2; mi++) {
                int r = wm * 32 + mi * 16 + g;
                af[mi][0] = f2tf32(as[r * LDSW + ks + tg]);
                af[mi][1] = f2tf32(as[(r + 8) * LDSW + ks + tg]);
                af[mi][2] = f2tf32(as[r * LDSW + ks + tg + 4]);
                af[mi][3] = f2tf32(as[(r + 8) * LDSW + ks + tg + 4]);
            }
#pragma unroll
            for (int ni = 0; ni < NI; ni++) {
                int cb = wn * WN + ni * 8 + g;
                bf[ni][0] = f2tf32(bs[cb * LDSW + ks + tg]);
                bf[ni][1] = f2tf32(bs[cb * LDSW + ks + tg + 4]);
            }
#pragma unroll
            for (int mi = 0; mi < 2; mi++)
#pragma unroll
                for (int ni = 0; ni < NI; ni++)
                    mma_tf32(acc[mi][ni], af[mi], bf[ni]);
        }
    }

    if (score_parts != nullptr) {
        // Fused additive-attention score epilogue (BM == 64):
        // rows of this block are b = 0..63 of s = m0/64.
        __syncthreads();               // all stages consumed; reuse smem
        float* sred = smem;            // [64 rows][NWM*4 warp-col slots]
        constexpr int NWN = 8 / NWM;   // number of wn values
#pragma unroll
        for (int mi = 0; mi < 2; mi++) {
#pragma unroll
            for (int sub = 0; sub < 2; sub++) {
                int rowl = wm * 32 + mi * 16 + g + sub * 8;    // 0..63
                float sum = 0.0f;
#pragma unroll
                for (int ni = 0; ni < NI; ni++) {
#pragma unroll
                    for (int c2 = 0; c2 < 2; c2++) {
                        int col = n0 + wn * WN + ni * 8 + tg * 2 + c2;
                        float v = acc[mi][ni][sub * 2 + c2];
                        sum += tanh_fast(v + dp[rowl * Ad + col]) * vw[col];
                    }
                }
                // reduce over tg (lanes g*4 + 0..3)
                sum += __shfl_xor_sync(0xffffffffu, sum, 1);
                sum += __shfl_xor_sync(0xffffffffu, sum, 2);
                if (tg == 0) sred[rowl * NWN + wn] = sum;
            }
        }
        __syncthreads();
        if (tid < 64) {
            float s = 0.0f;
#pragma unroll
            for (int w = 0; w < NWN; w++) s += sred[tid * NWN + w];
            score_parts[(size_t)blockIdx.x * (Sq * Bz) + (m0 >> 6) * Bz + tid] = s;
        }
        return;
    }

#pragma unroll
    for (int mi = 0; mi < 2; mi++) {
        int row = m0 + wm * 32 + mi * 16 + g;
#pragma unroll
        for (int ni = 0; ni < NI; ni++) {
            int col = n0 + wn * WN + ni * 8 + tg * 2;
            float b0 = bias ? bias[col]     : 0.0f;
            float b1 = bias ? bias[col + 1] : 0.0f;
            C[(size_t)row * N + col]           = acc[mi][ni][0] + b0;
            C[(size_t)row * N + col + 1]       = acc[mi][ni][1] + b1;
            C[(size_t)(row + 8) * N + col]     = acc[mi][ni][2] + b0;
            C[(size_t)(row + 8) * N + col + 1] = acc[mi][ni][3] + b1;
        }
    }
}

#define GEMM_SMALL  gemm_cp<64,128,32,3>
#define SMEM_SMALL  ((64 + 128) * LDSW * 4 * 3)

// ---------------------------------------------------------------------------
// prep: embedding gather -> x0[:, :512]  AND dense dp = sum of DPSPLIT parts.
// Grid 128 x 256 (32768 threads; both jobs have 64*512 elements).
// ---------------------------------------------------------------------------
__global__ void prep_kernel(const int* __restrict__ token,
                            const float* __restrict__ emb,
                            const float* __restrict__ dp_parts,
                            float* __restrict__ x0,
                            float* __restrict__ dp)
{
    int id = blockIdx.x * 256 + threadIdx.x;   // 0..32767
    int b = id >> 9;
    int j = id & 511;
    x0[b * 2560 + j] = emb[(size_t)token[b] * Ed + j];
    float s = 0.0f;
#pragma unroll
    for (int z = 0; z < DPSPLIT; z++)
        s += dp_parts[z * (Bz * Ad) + id];
    dp[id] = s;
}

// ---------------------------------------------------------------------------
// Fused softmax + context. Grid (2048/256, 64), 256 threads.
// Each block: sum score partials -> softmax over s (redundant per chunk) ->
// context for its 256-d chunk -> x0[:,512:], fcin[:,1024:]; chunk 0 writes alpha.
// ---------------------------------------------------------------------------
__global__ void __launch_bounds__(256)
ctx_softmax_kernel(const float* __restrict__ score_parts,
                   const float* __restrict__ enc,
                   float* __restrict__ x0,
                   float* __restrict__ fcin,
                   float* __restrict__ out_alpha)
{
    const int b    = blockIdx.y;
    const int tid  = threadIdx.x;
    const int warp = tid >> 5;
    const int lane = tid & 31;

    __shared__ float al[Sq];
    __shared__ float red[8];

    float x = -CUDART_INF_F;
    if (tid < Sq) {
        float s = 0.0f;
#pragma unroll
        for (int p = 0; p < NEB; p++)
            s += score_parts[(size_t)p * (Sq * Bz) + tid * Bz + b];
        x = s;
    }
    float m = x;
#pragma unroll
    for (int o = 16; o; o >>= 1) m = fmaxf(m, __shfl_xor_sync(0xffffffffu, m, o));
    if (lane == 0) red[warp] = m;
    __syncthreads();
    m = red[0];
#pragma unroll
    for (int w = 1; w < 8; w++) m = fmaxf(m, red[w]);
    __syncthreads();

    float e = (tid < Sq) ? __expf(x - m) : 0.0f;
    float ssum = e;
#pragma unroll
    for (int o = 16; o; o >>= 1) ssum += __shfl_xor_sync(0xffffffffu, ssum, o);
    if (lane == 0) red[warp] = ssum;
    __syncthreads();
    ssum = red[0];
#pragma unroll
    for (int w = 1; w < 8; w++) ssum += red[w];

    float a = e / ssum;
    if (tid < Sq) {
        al[tid] = a;
        if (blockIdx.x == 0) out_alpha[b * Sq + tid] = a;
    }
    __syncthreads();

    int d = blockIdx.x * 256 + tid;
    const float* ep = enc + (size_t)b * 2048 + d;
    float acc = 0.0f;
#pragma unroll 4
    for (int s = 0; s < Sq; s++)
        acc += al[s] * ep[(size_t)s * Bz * 2048];
    x0[b * 2560 + Ed + d]   = acc;
    fcin[b * 3072 + Hd + d] = acc;
}

// ---------------------------------------------------------------------------
// LSTM cell elementwise; sums NSPLIT gate partials, adds biases.
// ---------------------------------------------------------------------------
__device__ __forceinline__ float sigm(float x) { return 1.0f / (1.0f + __expf(-x)); }

__global__ void cell_kernel(const float* __restrict__ gates,
                            const float* __restrict__ bih,
                            const float* __restrict__ bhh,
                            const float* __restrict__ c_prev,
                            float* __restrict__ h_scratch, int h_stride,
                            float* __restrict__ h_out,
                            float* __restrict__ c_out)
{
    int id = blockIdx.x * 256 + threadIdx.x;   // 0..65535
    int b = id >> 10;
    int j = id & 1023;
    float gi = bih[j]        + bhh[j];
    float gf = bih[1024 + j] + bhh[1024 + j];
    float gg = bih[2048 + j] + bhh[2048 + j];
    float go = bih[3072 + j] + bhh[3072 + j];
#pragma unroll
    for (int z = 0; z < NSPLIT; z++) {
        const float* gr = gates + (size_t)z * (Bz * 4096) + (size_t)b * 4096;
        gi += gr[j];
        gf += gr[1024 + j];
        gg += gr[2048 + j];
        go += gr[3072 + j];
    }
    float i = sigm(gi), f = sigm(gf), o = sigm(go);
    float c = f * c_prev[id] + i * tanhf(gg);
    float h = o * tanhf(c);
    h_scratch[b * h_stride + j] = h;
    h_out[id] = h;
    c_out[id] = c;
}

// ---------------------------------------------------------------------------
// launch
// ---------------------------------------------------------------------------
extern "C" void kernel_launch(void* const* d_in, const int* in_sizes, int n_in,
                              void* d_out, int out_size)
{
    const int*   token  = (const int*)  d_in[0];
    const float* hidden = (const float*)d_in[1];   // (2,64,1024)
    const float* cell   = (const float*)d_in[2];   // (2,64,1024)
    const float* enc    = (const float*)d_in[3];   // (128,64,2048)
    const float* emb    = (const float*)d_in[4];   // (32000,512)
    const float* W_enc  = (const float*)d_in[5];   // (512,2048)
    const float* W_dec  = (const float*)d_in[6];   // (512,1024)
    const float* v_w    = (const float*)d_in[7];   // (512)
    const float* W_ih0  = (const float*)d_in[8];   // (4096,2560)
    const float* W_hh0  = (const float*)d_in[9];   // (4096,1024)
    const float* b_ih0  = (const float*)d_in[10];
    const float* b_hh0  = (const float*)d_in[11];
    const float* W_ih1  = (const float*)d_in[12];  // (4096,1024)
    const float* W_hh1  = (const float*)d_in[13];  // (4096,1024)
    const float* b_ih1  = (const float*)d_in[14];
    const float* b_hh1  = (const float*)d_in[15];
    const float* fc_W   = (const float*)d_in[16];  // (32000,3072)
    const float* fc_b   = (const float*)d_in[17];  // (32000)

    float* scratch = nullptr;
    cudaGetSymbolAddress((void**)&scratch, g_scratch);

    float* dp_parts = scratch + OFF_DPP;
    float* dp       = scratch + OFF_DP;
    float* scorep   = scratch + OFF_SCOREP;
    float* x0       = scratch + OFF_X0;
    float* gates    = scratch + OFF_GATES;
    float* h0       = scratch + OFF_H0;
    float* fcin     = scratch + OFF_FCIN;

    float* out        = (float*)d_out;
    float* out_logits = out;                                   // 64*32000
    float* out_hidden = out + (size_t)Bz * Vv;                 // 2*64*1024
    float* out_cell   = out_hidden + 2 * Bz * Hd;              // 2*64*1024
    float* out_alpha  = out_cell + 2 * Bz * Hd;                // 64*128

    cudaFuncSetAttribute(GEMM_SMALL, cudaFuncAttributeMaxDynamicSharedMemorySize, SMEM_SMALL);

    // 1) dec_proj partials = hidden[-1] @ W_dec^T   (split-K x4, 16 CTAs)
    GEMM_SMALL<<<dim3(Ad / 128, 1, DPSPLIT), 256, SMEM_SMALL>>>(
        hidden + (size_t)Bz * Hd, W_dec, Hd,
        nullptr, nullptr, 0, nullptr, dp_parts, Ad, 32 / DPSPLIT, Bz * Ad,
        nullptr, nullptr, nullptr);

    // 2) prep: embedding -> x0[:, :512]; dense dp
    prep_kernel<<<128, 256>>>(token, emb, dp_parts, x0, dp);

    // 3) energy GEMM with fused score epilogue -> score_parts (512 CTAs)
    GEMM_SMALL<<<dim3(Ad / 128, (Sq * Bz) / 64, 1), 256, SMEM_SMALL>>>(
        enc, W_enc, 2 * Hd,
        nullptr, nullptr, 0, nullptr, nullptr, Ad, 64, 0,
        dp, v_w, scorep);

    // 4) fused softmax + context -> x0[:,512:], fcin[:,1024:], out_alpha
    ctx_softmax_kernel<<<dim3(2048 / 256, Bz), 256>>>(scorep, enc, x0, fcin, out_alpha);

    // 5) gates0 partials = x0 @ W_ih0^T + hidden[0] @ W_hh0^T  (split-K x8)
    GEMM_SMALL<<<dim3(4096 / 128, 1, NSPLIT), 256, SMEM_SMALL>>>(
        x0, W_ih0, Ed + 2 * Hd,
        hidden, W_hh0, Hd, nullptr, gates, 4096, 112 / NSPLIT, Bz * 4096,
        nullptr, nullptr, nullptr);

    // 6) LSTM cell 0 -> h0 (scratch), out_hidden[0], out_cell[0]
    cell_kernel<<<(Bz * Hd) / 256, 256>>>(gates, b_ih0, b_hh0, cell,
                                          h0, Hd, out_hidden, out_cell);

    // 7) gates1 partials = h0 @ W_ih1^T + hidden[1] @ W_hh1^T  (split-K x8)
    GEMM_SMALL<<<dim3(4096 / 128, 1, NSPLIT), 256, SMEM_SMALL>>>(
        h0, W_ih1, Hd,
        hidden + (size_t)Bz * Hd, W_hh1, Hd, nullptr, gates, 4096, 64 / NSPLIT, Bz * 4096,
        nullptr, nullptr, nullptr);

    // 8) LSTM cell 1 -> h1 into fcin[:, :1024], out_hidden[1], out_cell[1]
    cell_kernel<<<(Bz * Hd) / 256, 256>>>(gates, b_ih1, b_hh1, cell + (size_t)Bz * Hd,
                                          fcin, 3 * Hd,
                                          out_hidden + (size_t)Bz * Hd,
                                          out_cell + (size_t)Bz * Hd);

    // 9) logits = fcin @ fc_W^T + fc_b            (64,32000)
    GEMM_SMALL<<<dim3(Vv / 128, 1, 1), 256, SMEM_SMALL>>>(
        fcin, fc_W, 3 * Hd,
        nullptr, nullptr, 0, fc_b, out_logits, Vv, 96, 0,
        nullptr, nullptr, nullptr);
}